// round 2
// baseline (speedup 1.0000x reference)
#include <cuda_runtime.h>

#define KK 20
#define CC 96
#define TILE_P 32
#define NG 4
#define GROUP 48                 // 4 kt * 12 ct
#define NTHREADS (NG * GROUP)    // 192
#define K_T 5
#define C_T 8
#define MAX_BLOCKS 512

// persistent scratch (allocations forbidden)
__device__ float g_part[MAX_BLOCKS * KK * CC];   // per-block partial context
__device__ float g_pden[MAX_BLOCKS * KK];        // per-block partial denom

// ---------------------------------------------------------------------------
// packed f32x2 helpers (Blackwell FFMA2 path)
// ---------------------------------------------------------------------------
__device__ __forceinline__ unsigned long long pack2(float lo, float hi) {
    unsigned long long r;
    asm("mov.b64 %0, {%1, %2};" : "=l"(r) : "f"(lo), "f"(hi));
    return r;
}
__device__ __forceinline__ unsigned long long fma2(unsigned long long a,
                                                   unsigned long long b,
                                                   unsigned long long c) {
    unsigned long long d;
    asm("fma.rn.f32x2 %0, %1, %2, %3;" : "=l"(d) : "l"(a), "l"(b), "l"(c));
    return d;
}
__device__ __forceinline__ void unpack2(unsigned long long x, float& lo, float& hi) {
    asm("mov.b64 {%0, %1}, %2;" : "=f"(lo), "=f"(hi) : "l"(x));
}

// warp-cooperative lower_bound on sorted int array (4 ballot rounds for N=128K)
__device__ __forceinline__ int lower_bound_warp(const int* __restrict__ a,
                                                int n, int key) {
    int lane = threadIdx.x & 31;
    int lo = 0, hi = n;
    while (lo < hi) {
        int len = hi - lo;
        int chunk = (len + 31) >> 5;
        int pos = lo + lane * chunk;
        bool pred = (pos < hi) && (a[pos] < key);
        unsigned m = __ballot_sync(0xffffffffu, pred);
        int t = __popc(m);
        if (t == 0) { hi = lo; break; }
        int nlo = lo + (t - 1) * chunk + 1;
        int nhi = (t < 32) ? min(lo + t * chunk, hi) : hi;
        lo = nlo; hi = nhi;
    }
    return lo;
}

// ---------------------------------------------------------------------------
// Main fused pass: per block, accumulate partial[k,c] = sum_n exp(p[n,k])*f[n,c]
// and pden[k] = sum_n exp(p[n,k]) over the block's point range.
// ---------------------------------------------------------------------------
__global__ void __launch_bounds__(NTHREADS)
gather_kernel(const float* __restrict__ feats,
              const float* __restrict__ probs,
              const int*   __restrict__ bidx,
              int N, int splits) {
    __shared__ float4 sh_f[2][TILE_P][CC / 4];   // 24576 B
    __shared__ float  sh_e[2][TILE_P][KK];       // 5120 B
    __shared__ float  sh_red[KK * CC];           // 7680 B
    __shared__ float  sh_d[NG][KK];
    __shared__ int    sh_off[2];

    const int b = blockIdx.x / splits;
    const int s = blockIdx.x % splits;

    // per-block segment bounds via warp-cooperative binary search (warp 0)
    if (threadIdx.x < 32) {
        int lo0 = lower_bound_warp(bidx, N, b);
        int lo1 = lower_bound_warp(bidx, N, b + 1);
        if (threadIdx.x == 0) { sh_off[0] = lo0; sh_off[1] = lo1; }
    }
    __syncthreads();
    const int seg0 = sh_off[0];
    const int seg1 = sh_off[1];
    const int len  = seg1 - seg0;
    const int r0 = seg0 + (int)((long long)len * s / splits);
    const int r1 = seg0 + (int)((long long)len * (s + 1) / splits);

    const int tid = threadIdx.x;
    const int g   = tid / GROUP;
    const int gt  = tid % GROUP;
    const int kt  = gt / 12;
    const int ct  = gt % 12;

    unsigned long long acc[K_T][4];
#pragma unroll
    for (int j = 0; j < K_T; j++)
#pragma unroll
        for (int q = 0; q < 4; q++) acc[j][q] = 0ULL;
    float dacc[K_T];
#pragma unroll
    for (int j = 0; j < K_T; j++) dacc[j] = 0.0f;

    const float4* feats4 = reinterpret_cast<const float4*>(feats);
    const int tiles = (r1 - r0 + TILE_P - 1) / TILE_P;

    float4 rf[4];
    float  rp[4];

    // ---- prefetch tile 0 ----
    if (tiles > 0) {
        int base = r0;
#pragma unroll
        for (int j = 0; j < 4; j++) {
            int v = tid + j * NTHREADS;               // 0..767
            int p = v / (CC / 4), c4 = v % (CC / 4);
            int idx = base + p;
            rf[j] = (idx < r1) ? feats4[idx * (CC / 4) + c4]
                               : make_float4(0.f, 0.f, 0.f, 0.f);
        }
#pragma unroll
        for (int j = 0; j < 4; j++) {
            int v = tid + j * NTHREADS;
            rp[j] = -1e30f;
            if (v < TILE_P * KK) {
                int p = v / KK, k = v % KK;
                int idx = base + p;
                if (idx < r1) rp[j] = probs[idx * KK + k];
            }
        }
        // store tile 0 into buf 0
#pragma unroll
        for (int j = 0; j < 4; j++) {
            int v = tid + j * NTHREADS;
            int p = v / (CC / 4), c4 = v % (CC / 4);
            sh_f[0][p][c4] = rf[j];
        }
#pragma unroll
        for (int j = 0; j < 4; j++) {
            int v = tid + j * NTHREADS;
            if (v < TILE_P * KK) {
                int p = v / KK, k = v % KK;
                sh_e[0][p][k] = __expf(rp[j]);
            }
        }
        __syncthreads();
    }

    for (int t = 0; t < tiles; t++) {
        const int buf = t & 1;
        // prefetch next tile into registers (overlaps with compute)
        if (t + 1 < tiles) {
            int base = r0 + (t + 1) * TILE_P;
#pragma unroll
            for (int j = 0; j < 4; j++) {
                int v = tid + j * NTHREADS;
                int p = v / (CC / 4), c4 = v % (CC / 4);
                int idx = base + p;
                rf[j] = (idx < r1) ? feats4[idx * (CC / 4) + c4]
                                   : make_float4(0.f, 0.f, 0.f, 0.f);
            }
#pragma unroll
            for (int j = 0; j < 4; j++) {
                int v = tid + j * NTHREADS;
                rp[j] = -1e30f;
                if (v < TILE_P * KK) {
                    int p = v / KK, k = v % KK;
                    int idx = base + p;
                    if (idx < r1) rp[j] = probs[idx * KK + k];
                }
            }
        }

        // ---- rank-TILE_P update (FFMA2 path) ----
#pragma unroll
        for (int pp8 = 0; pp8 < TILE_P / NG; pp8++) {
            const int pp = g * (TILE_P / NG) + pp8;
            float4 fA = sh_f[buf][pp][ct * 2];
            float4 fB = sh_f[buf][pp][ct * 2 + 1];
            unsigned long long f01 = pack2(fA.x, fA.y);
            unsigned long long f23 = pack2(fA.z, fA.w);
            unsigned long long f45 = pack2(fB.x, fB.y);
            unsigned long long f67 = pack2(fB.z, fB.w);
#pragma unroll
            for (int j = 0; j < K_T; j++) {
                float e = sh_e[buf][pp][kt * K_T + j];
                unsigned long long e2 = pack2(e, e);
                acc[j][0] = fma2(e2, f01, acc[j][0]);
                acc[j][1] = fma2(e2, f23, acc[j][1]);
                acc[j][2] = fma2(e2, f45, acc[j][2]);
                acc[j][3] = fma2(e2, f67, acc[j][3]);
                if (ct == 0) dacc[j] += e;
            }
        }

        // stage next tile into the other buffer
        if (t + 1 < tiles) {
            const int nbuf = (t + 1) & 1;
#pragma unroll
            for (int j = 0; j < 4; j++) {
                int v = tid + j * NTHREADS;
                int p = v / (CC / 4), c4 = v % (CC / 4);
                sh_f[nbuf][p][c4] = rf[j];
            }
#pragma unroll
            for (int j = 0; j < 4; j++) {
                int v = tid + j * NTHREADS;
                if (v < TILE_P * KK) {
                    int p = v / KK, k = v % KK;
                    sh_e[nbuf][p][k] = __expf(rp[j]);
                }
            }
        }
        __syncthreads();
    }

    // ---- cross-group reduction into sh_red, then write partials ----
    float accf[K_T][C_T];
#pragma unroll
    for (int j = 0; j < K_T; j++)
#pragma unroll
        for (int q = 0; q < 4; q++)
            unpack2(acc[j][q], accf[j][2 * q], accf[j][2 * q + 1]);

    if (ct == 0) {
#pragma unroll
        for (int j = 0; j < K_T; j++) sh_d[g][kt * K_T + j] = dacc[j];
    }
    if (g == 1) {
#pragma unroll
        for (int j = 0; j < K_T; j++) {
            int k = kt * K_T + j;
#pragma unroll
            for (int q = 0; q < C_T; q++)
                sh_red[k * CC + ct * C_T + q] = accf[j][q];
        }
    }
    __syncthreads();
    if (g == 2) {
#pragma unroll
        for (int j = 0; j < K_T; j++) {
            int k = kt * K_T + j;
#pragma unroll
            for (int q = 0; q < C_T; q++)
                sh_red[k * CC + ct * C_T + q] += accf[j][q];
        }
    }
    __syncthreads();
    if (g == 3) {
#pragma unroll
        for (int j = 0; j < K_T; j++) {
            int k = kt * K_T + j;
#pragma unroll
            for (int q = 0; q < C_T; q++)
                sh_red[k * CC + ct * C_T + q] += accf[j][q];
        }
    }
    __syncthreads();
    if (g == 0) {
        float* outp = g_part + blockIdx.x * (KK * CC);
#pragma unroll
        for (int j = 0; j < K_T; j++) {
            int k = kt * K_T + j;
#pragma unroll
            for (int q = 0; q < C_T; q++)
                outp[k * CC + ct * C_T + q] =
                    accf[j][q] + sh_red[k * CC + ct * C_T + q];
        }
        if (ct == 0) {
#pragma unroll
            for (int j = 0; j < K_T; j++) {
                int k = kt * K_T + j;
                g_pden[blockIdx.x * KK + k] =
                    dacc[j] + sh_d[1][k] + sh_d[2][k] + sh_d[3][k];
            }
        }
    }
}

// ---------------------------------------------------------------------------
// Reduce: out[b,k,c] = sum_s part[b,s,k,c] / sum_s pden[b,s,k]
// one block per (b,k), 96 threads (one per c)
// ---------------------------------------------------------------------------
__global__ void reduce_kernel(float* __restrict__ out, int splits) {
    const int bk = blockIdx.x;
    const int b = bk / KK, k = bk % KK;
    __shared__ float sd;

    if (threadIdx.x < 32) {
        float d = 0.0f;
        for (int s = threadIdx.x; s < splits; s += 32)
            d += g_pden[(b * splits + s) * KK + k];
#pragma unroll
        for (int o = 16; o > 0; o >>= 1)
            d += __shfl_down_sync(0xffffffffu, d, o);
        if (threadIdx.x == 0) sd = d;
    }
    __syncthreads();

    const int c = threadIdx.x;
    float v = 0.0f;
    for (int s = 0; s < splits; s++)
        v += g_part[(b * splits + s) * (KK * CC) + k * CC + c];
    float d = sd;
    out[b * (KK * CC) + k * CC + c] = (d > 0.0f) ? v / d : 0.0f;
}

// ---------------------------------------------------------------------------
extern "C" void kernel_launch(void* const* d_in, const int* in_sizes, int n_in,
                              void* d_out, int out_size) {
    const float* feats = (const float*)d_in[0];   // [N, C]
    const float* probs = (const float*)d_in[1];   // [N, K]
    const int*   bidx  = (const int*)d_in[3];     // [N], sorted
    float* out = (float*)d_out;                   // [B, K, C]

    const int N = in_sizes[3];
    const int B = out_size / (KK * CC);

    int splits = (296 + B - 1) / B;
    if (splits < 1) splits = 1;
    while (B * splits > MAX_BLOCKS) splits--;
    if (splits < 1) splits = 1;

    gather_kernel<<<B * splits, NTHREADS>>>(feats, probs, bidx, N, splits);
    reduce_kernel<<<B * KK, CC>>>(out, splits);
}

// round 3
// speedup vs baseline: 1.5064x; 1.5064x over previous
#include <cuda_runtime.h>

#define KK 20
#define CC 96
#define TILE_P 16
#define NG 4
#define GROUP 48                 // 4 kt * 12 ct
#define NTHREADS (NG * GROUP)    // 192
#define K_T 5
#define C_T 8
#define SPLITS 37
#define MAX_BLOCKS 400
#define NSTAGE 3

// persistent scratch (allocations forbidden)
__device__ float g_part[MAX_BLOCKS * KK * CC];
__device__ float g_pden[MAX_BLOCKS * KK];

// ---------------------------------------------------------------------------
// f32x2 helpers (Blackwell FFMA2 path)
// ---------------------------------------------------------------------------
__device__ __forceinline__ unsigned long long pack2(float lo, float hi) {
    unsigned long long r;
    asm("mov.b64 %0, {%1, %2};" : "=l"(r) : "f"(lo), "f"(hi));
    return r;
}
__device__ __forceinline__ unsigned long long fma2(unsigned long long a,
                                                   unsigned long long b,
                                                   unsigned long long c) {
    unsigned long long d;
    asm("fma.rn.f32x2 %0, %1, %2, %3;" : "=l"(d) : "l"(a), "l"(b), "l"(c));
    return d;
}
__device__ __forceinline__ void unpack2(unsigned long long x, float& lo, float& hi) {
    asm("mov.b64 {%0, %1}, %2;" : "=f"(lo), "=f"(hi) : "l"(x));
}

__device__ __forceinline__ unsigned smem_u32(const void* p) {
    return (unsigned)__cvta_generic_to_shared(p);
}
__device__ __forceinline__ void cp16(unsigned dst, const void* src) {
    asm volatile("cp.async.ca.shared.global [%0], [%1], 16;"
                 :: "r"(dst), "l"(src));
}
__device__ __forceinline__ void cp_commit() {
    asm volatile("cp.async.commit_group;");
}
__device__ __forceinline__ void cp_wait1() {
    asm volatile("cp.async.wait_group 1;");
}
__device__ __forceinline__ void cp_wait0() {
    asm volatile("cp.async.wait_group 0;");
}

// warp-cooperative lower_bound on sorted int array
__device__ __forceinline__ int lower_bound_warp(const int* __restrict__ a,
                                                int n, int key) {
    int lane = threadIdx.x & 31;
    int lo = 0, hi = n;
    while (lo < hi) {
        int len = hi - lo;
        int chunk = (len + 31) >> 5;
        int pos = lo + lane * chunk;
        bool pred = (pos < hi) && (a[pos] < key);
        unsigned m = __ballot_sync(0xffffffffu, pred);
        int t = __popc(m);
        if (t == 0) { hi = lo; break; }
        int nlo = lo + (t - 1) * chunk + 1;
        int nhi = (t < 32) ? min(lo + t * chunk, hi) : hi;
        lo = nlo; hi = nhi;
    }
    return lo;
}

// ---------------------------------------------------------------------------
__global__ void __launch_bounds__(NTHREADS)
gather_kernel(const float* __restrict__ feats,
              const float* __restrict__ probs,
              const int*   __restrict__ bidx,
              int N) {
    __shared__ float raw_f[NSTAGE][TILE_P][CC];   // 18432 B
    __shared__ float raw_p[NSTAGE][TILE_P][KK];   //  3840 B
    __shared__ float sh_e[TILE_P][KK];            //  1280 B
    __shared__ float sh_red[KK * CC];             //  7680 B
    __shared__ float sh_dk[KK];
    __shared__ int   sh_off[2];

    const int b = blockIdx.x / SPLITS;
    const int s = blockIdx.x % SPLITS;

    if (threadIdx.x < 32) {
        int lo0 = lower_bound_warp(bidx, N, b);
        int lo1 = lower_bound_warp(bidx, N, b + 1);
        if (threadIdx.x == 0) { sh_off[0] = lo0; sh_off[1] = lo1; }
    }
    if (threadIdx.x < KK) sh_dk[threadIdx.x] = 0.0f;
    __syncthreads();
    const int seg0 = sh_off[0];
    const int seg1 = sh_off[1];
    const int len  = seg1 - seg0;
    const int r0 = seg0 + (int)((long long)len * s / SPLITS);
    const int r1 = seg0 + (int)((long long)len * (s + 1) / SPLITS);

    const int tid = threadIdx.x;
    const int g   = tid / GROUP;
    const int gt  = tid % GROUP;
    const int kt  = gt / 12;
    const int ct  = gt % 12;

    unsigned long long acc[K_T][4];
#pragma unroll
    for (int j = 0; j < K_T; j++)
#pragma unroll
        for (int q = 0; q < 4; q++) acc[j][q] = 0ULL;
    float dacc0 = 0.0f, dacc1 = 0.0f;
    const int k1 = tid % KK;
    const int k2 = (tid + NTHREADS) % KK;

    const int T = (r1 - r0 + TILE_P - 1) / TILE_P;

    // precomputed per-thread cp.async slots
    const int fp0 = tid / (CC / 4), fc0 = tid % (CC / 4);
    const int fp1 = (tid + NTHREADS) / (CC / 4), fc1 = (tid + NTHREADS) % (CC / 4);
    const int pp0 = tid / (KK / 4), pq0 = tid % (KK / 4);   // 80 slots

    // ---- issue tiles 0,1 ----
#pragma unroll
    for (int tt = 0; tt < 2; tt++) {
        const int base = r0 + tt * TILE_P;
        {
            int idx = min(base + fp0, N - 1);
            cp16(smem_u32(&raw_f[tt][fp0][fc0 * 4]), feats + idx * CC + fc0 * 4);
            idx = min(base + fp1, N - 1);
            cp16(smem_u32(&raw_f[tt][fp1][fc1 * 4]), feats + idx * CC + fc1 * 4);
        }
        if (tid < TILE_P * (KK / 4)) {
            int idx = min(base + pp0, N - 1);
            cp16(smem_u32(&raw_p[tt][pp0][pq0 * 4]), probs + idx * KK + pq0 * 4);
        }
        cp_commit();
    }

    for (int t = 0; t < T; t++) {
        const int st = t % NSTAGE;
        const int base = r0 + t * TILE_P;
        cp_wait1();          // tile t arrived
        __syncthreads();

        // convert probs -> exp (masked), accumulate denom
        {
            int v = tid;
            int p = v / KK, k = v % KK;
            float e = (base + p < r1) ? __expf(raw_p[st][p][k]) : 0.0f;
            sh_e[p][k] = e;
            dacc0 += e;
            v = tid + NTHREADS;
            if (v < TILE_P * KK) {
                p = v / KK; k = v % KK;
                e = (base + p < r1) ? __expf(raw_p[st][p][k]) : 0.0f;
                sh_e[p][k] = e;
                dacc1 += e;
            }
        }
        __syncthreads();

        // ---- rank-16 update (FFMA2) ----
#pragma unroll
        for (int p = 0; p < TILE_P / NG; p++) {
            const int pp = g * (TILE_P / NG) + p;
            const ulonglong2* rowf =
                reinterpret_cast<const ulonglong2*>(&raw_f[st][pp][ct * C_T]);
            ulonglong2 fA = rowf[0];   // c0..c3 as two f32x2
            ulonglong2 fB = rowf[1];   // c4..c7
#pragma unroll
            for (int j = 0; j < K_T; j++) {
                float e = sh_e[pp][kt * K_T + j];
                unsigned long long e2 = pack2(e, e);
                acc[j][0] = fma2(e2, fA.x, acc[j][0]);
                acc[j][1] = fma2(e2, fA.y, acc[j][1]);
                acc[j][2] = fma2(e2, fB.x, acc[j][2]);
                acc[j][3] = fma2(e2, fB.y, acc[j][3]);
            }
        }

        // issue tile t+2
        if (t + 2 < T) {
            const int nst = (t + 2) % NSTAGE;
            const int nb = r0 + (t + 2) * TILE_P;
            int idx = min(nb + fp0, N - 1);
            cp16(smem_u32(&raw_f[nst][fp0][fc0 * 4]), feats + idx * CC + fc0 * 4);
            idx = min(nb + fp1, N - 1);
            cp16(smem_u32(&raw_f[nst][fp1][fc1 * 4]), feats + idx * CC + fc1 * 4);
            if (tid < TILE_P * (KK / 4)) {
                idx = min(nb + pp0, N - 1);
                cp16(smem_u32(&raw_p[nst][pp0][pq0 * 4]), probs + idx * KK + pq0 * 4);
            }
        }
        cp_commit();
    }
    cp_wait0();
    __syncthreads();

    // ---- denom reduction ----
    atomicAdd(&sh_dk[k1], dacc0);
    if (tid + NTHREADS < (TILE_P * KK / (TILE_P * KK / (2 * NTHREADS - NTHREADS)) , 320))  // tid<128
        ;
    if (tid < TILE_P * KK - NTHREADS)   // tid < 128
        atomicAdd(&sh_dk[k2], dacc1);

    // ---- cross-group reduction of acc into sh_red ----
    float accf[K_T][C_T];
#pragma unroll
    for (int j = 0; j < K_T; j++)
#pragma unroll
        for (int q = 0; q < 4; q++)
            unpack2(acc[j][q], accf[j][2 * q], accf[j][2 * q + 1]);

    if (g == 1) {
#pragma unroll
        for (int j = 0; j < K_T; j++) {
            int k = kt * K_T + j;
#pragma unroll
            for (int q = 0; q < C_T; q++)
                sh_red[k * CC + ct * C_T + q] = accf[j][q];
        }
    }
    __syncthreads();
    if (g == 2) {
#pragma unroll
        for (int j = 0; j < K_T; j++) {
            int k = kt * K_T + j;
#pragma unroll
            for (int q = 0; q < C_T; q++)
                sh_red[k * CC + ct * C_T + q] += accf[j][q];
        }
    }
    __syncthreads();
    if (g == 3) {
#pragma unroll
        for (int j = 0; j < K_T; j++) {
            int k = kt * K_T + j;
#pragma unroll
            for (int q = 0; q < C_T; q++)
                sh_red[k * CC + ct * C_T + q] += accf[j][q];
        }
    }
    __syncthreads();
    if (g == 0) {
        float* outp = g_part + blockIdx.x * (KK * CC);
#pragma unroll
        for (int j = 0; j < K_T; j++) {
            int k = kt * K_T + j;
#pragma unroll
            for (int q = 0; q < C_T; q++)
                outp[k * CC + ct * C_T + q] =
                    accf[j][q] + sh_red[k * CC + ct * C_T + q];
        }
    }
    if (tid < KK)
        g_pden[blockIdx.x * KK + tid] = sh_dk[tid];
}

// ---------------------------------------------------------------------------
// out[b,k,c] = sum_s part / sum_s pden ; SPLITS compile-time -> full unroll
// ---------------------------------------------------------------------------
__global__ void reduce_kernel(float* __restrict__ out, int total) {
    const int i = blockIdx.x * blockDim.x + threadIdx.x;
    if (i >= total) return;
    const int c = i % CC;
    const int k = (i / CC) % KK;
    const int b = i / (KK * CC);

    float v = 0.0f, d = 0.0f;
#pragma unroll
    for (int s = 0; s < SPLITS; s++)
        v += g_part[((b * SPLITS + s) * KK + k) * CC + c];
#pragma unroll
    for (int s = 0; s < SPLITS; s++)
        d += g_pden[(b * SPLITS + s) * KK + k];
    out[i] = (d > 0.0f) ? v / d : 0.0f;
}

// ---------------------------------------------------------------------------
extern "C" void kernel_launch(void* const* d_in, const int* in_sizes, int n_in,
                              void* d_out, int out_size) {
    const float* feats = (const float*)d_in[0];   // [N, C]
    const float* probs = (const float*)d_in[1];   // [N, K]
    const int*   bidx  = (const int*)d_in[3];     // [N], sorted
    float* out = (float*)d_out;                   // [B, K, C]

    const int N = in_sizes[3];
    const int B = out_size / (KK * CC);

    gather_kernel<<<B * SPLITS, NTHREADS>>>(feats, probs, bidx, N);
    reduce_kernel<<<(out_size + 127) / 128, 128>>>(out, out_size);
}

// round 4
// speedup vs baseline: 1.5851x; 1.0522x over previous
#include <cuda_runtime.h>

#define KK 20
#define CC 96
#define TILE_P 16
#define NG 4
#define GROUP 48                 // 4 kt * 12 ct
#define NTHREADS (NG * GROUP)    // 192
#define K_T 5
#define C_T 8
#define SPLITS 37
#define MAX_BLOCKS 400
#define NSTAGE 3

// persistent scratch (allocations forbidden)
__device__ float g_part[MAX_BLOCKS * KK * CC];
__device__ float g_pden[MAX_BLOCKS * KK];

// ---------------------------------------------------------------------------
// f32x2 helpers (Blackwell FFMA2 path)
// ---------------------------------------------------------------------------
__device__ __forceinline__ unsigned long long pack2(float lo, float hi) {
    unsigned long long r;
    asm("mov.b64 %0, {%1, %2};" : "=l"(r) : "f"(lo), "f"(hi));
    return r;
}
__device__ __forceinline__ unsigned long long fma2(unsigned long long a,
                                                   unsigned long long b,
                                                   unsigned long long c) {
    unsigned long long d;
    asm("fma.rn.f32x2 %0, %1, %2, %3;" : "=l"(d) : "l"(a), "l"(b), "l"(c));
    return d;
}
__device__ __forceinline__ void unpack2(unsigned long long x, float& lo, float& hi) {
    asm("mov.b64 {%0, %1}, %2;" : "=f"(lo), "=f"(hi) : "l"(x));
}

__device__ __forceinline__ unsigned smem_u32(const void* p) {
    return (unsigned)__cvta_generic_to_shared(p);
}
__device__ __forceinline__ void cp16(unsigned dst, const void* src) {
    asm volatile("cp.async.ca.shared.global [%0], [%1], 16;"
                 :: "r"(dst), "l"(src));
}
__device__ __forceinline__ void cp_commit() {
    asm volatile("cp.async.commit_group;");
}
__device__ __forceinline__ void cp_wait1() {
    asm volatile("cp.async.wait_group 1;");
}
__device__ __forceinline__ void cp_wait0() {
    asm volatile("cp.async.wait_group 0;");
}

// warp-cooperative lower_bound on sorted int array
__device__ __forceinline__ int lower_bound_warp(const int* __restrict__ a,
                                                int n, int key) {
    int lane = threadIdx.x & 31;
    int lo = 0, hi = n;
    while (lo < hi) {
        int len = hi - lo;
        int chunk = (len + 31) >> 5;
        int pos = lo + lane * chunk;
        bool pred = (pos < hi) && (a[pos] < key);
        unsigned m = __ballot_sync(0xffffffffu, pred);
        int t = __popc(m);
        if (t == 0) { hi = lo; break; }
        int nlo = lo + (t - 1) * chunk + 1;
        int nhi = (t < 32) ? min(lo + t * chunk, hi) : hi;
        lo = nlo; hi = nhi;
    }
    return lo;
}

// ---------------------------------------------------------------------------
__global__ void __launch_bounds__(NTHREADS)
gather_kernel(const float* __restrict__ feats,
              const float* __restrict__ probs,
              const int*   __restrict__ bidx,
              int N) {
    __shared__ float raw_f[NSTAGE][TILE_P][CC];   // 18432 B
    __shared__ float raw_p[NSTAGE][TILE_P][KK];   //  3840 B
    __shared__ float sh_e[TILE_P][KK];            //  1280 B
    __shared__ float sh_red[KK * CC];             //  7680 B
    __shared__ float sh_dk[KK];
    __shared__ int   sh_off[2];

    const int b = blockIdx.x / SPLITS;
    const int s = blockIdx.x % SPLITS;

    if (threadIdx.x < 32) {
        int lo0 = lower_bound_warp(bidx, N, b);
        int lo1 = lower_bound_warp(bidx, N, b + 1);
        if (threadIdx.x == 0) { sh_off[0] = lo0; sh_off[1] = lo1; }
    }
    if (threadIdx.x < KK) sh_dk[threadIdx.x] = 0.0f;
    __syncthreads();
    const int seg0 = sh_off[0];
    const int seg1 = sh_off[1];
    const int len  = seg1 - seg0;
    const int r0 = seg0 + (int)((long long)len * s / SPLITS);
    const int r1 = seg0 + (int)((long long)len * (s + 1) / SPLITS);

    const int tid = threadIdx.x;
    const int g   = tid / GROUP;
    const int gt  = tid % GROUP;
    const int kt  = gt / 12;
    const int ct  = gt % 12;

    unsigned long long acc[K_T][4];
#pragma unroll
    for (int j = 0; j < K_T; j++)
#pragma unroll
        for (int q = 0; q < 4; q++) acc[j][q] = 0ULL;
    float dacc0 = 0.0f, dacc1 = 0.0f;
    const int k1 = tid % KK;
    const int k2 = (tid + NTHREADS) % KK;

    const int T = (r1 - r0 + TILE_P - 1) / TILE_P;

    // precomputed per-thread cp.async slots
    const int fp0 = tid / (CC / 4), fc0 = tid % (CC / 4);
    const int fp1 = (tid + NTHREADS) / (CC / 4), fc1 = (tid + NTHREADS) % (CC / 4);
    const int pp0 = tid / (KK / 4), pq0 = tid % (KK / 4);   // 80 slots

    // ---- issue tiles 0,1 ----
#pragma unroll
    for (int tt = 0; tt < 2; tt++) {
        const int base = r0 + tt * TILE_P;
        {
            int idx = min(base + fp0, N - 1);
            cp16(smem_u32(&raw_f[tt][fp0][fc0 * 4]), feats + idx * CC + fc0 * 4);
            idx = min(base + fp1, N - 1);
            cp16(smem_u32(&raw_f[tt][fp1][fc1 * 4]), feats + idx * CC + fc1 * 4);
        }
        if (tid < TILE_P * (KK / 4)) {
            int idx = min(base + pp0, N - 1);
            cp16(smem_u32(&raw_p[tt][pp0][pq0 * 4]), probs + idx * KK + pq0 * 4);
        }
        cp_commit();
    }

    for (int t = 0; t < T; t++) {
        const int st = t % NSTAGE;
        const int base = r0 + t * TILE_P;
        cp_wait1();          // tile t arrived
        __syncthreads();

        // convert probs -> exp (masked), accumulate denom
        {
            int v = tid;
            int p = v / KK, k = v % KK;
            float e = (base + p < r1) ? __expf(raw_p[st][p][k]) : 0.0f;
            sh_e[p][k] = e;
            dacc0 += e;
            v = tid + NTHREADS;
            if (v < TILE_P * KK) {
                p = v / KK; k = v % KK;
                e = (base + p < r1) ? __expf(raw_p[st][p][k]) : 0.0f;
                sh_e[p][k] = e;
                dacc1 += e;
            }
        }
        __syncthreads();

        // ---- rank-16 update (FFMA2) ----
#pragma unroll
        for (int p = 0; p < TILE_P / NG; p++) {
            const int pp = g * (TILE_P / NG) + p;
            const ulonglong2* rowf =
                reinterpret_cast<const ulonglong2*>(&raw_f[st][pp][ct * C_T]);
            ulonglong2 fA = rowf[0];   // c0..c3 as two f32x2
            ulonglong2 fB = rowf[1];   // c4..c7
#pragma unroll
            for (int j = 0; j < K_T; j++) {
                float e = sh_e[pp][kt * K_T + j];
                unsigned long long e2 = pack2(e, e);
                acc[j][0] = fma2(e2, fA.x, acc[j][0]);
                acc[j][1] = fma2(e2, fA.y, acc[j][1]);
                acc[j][2] = fma2(e2, fB.x, acc[j][2]);
                acc[j][3] = fma2(e2, fB.y, acc[j][3]);
            }
        }

        // issue tile t+2
        if (t + 2 < T) {
            const int nst = (t + 2) % NSTAGE;
            const int nb = r0 + (t + 2) * TILE_P;
            int idx = min(nb + fp0, N - 1);
            cp16(smem_u32(&raw_f[nst][fp0][fc0 * 4]), feats + idx * CC + fc0 * 4);
            idx = min(nb + fp1, N - 1);
            cp16(smem_u32(&raw_f[nst][fp1][fc1 * 4]), feats + idx * CC + fc1 * 4);
            if (tid < TILE_P * (KK / 4)) {
                idx = min(nb + pp0, N - 1);
                cp16(smem_u32(&raw_p[nst][pp0][pq0 * 4]), probs + idx * KK + pq0 * 4);
            }
        }
        cp_commit();
    }
    cp_wait0();
    __syncthreads();

    // ---- denom reduction ----
    atomicAdd(&sh_dk[k1], dacc0);
    if (tid + NTHREADS < (TILE_P * KK / (TILE_P * KK / (2 * NTHREADS - NTHREADS)) , 320))  // tid<128
        ;
    if (tid < TILE_P * KK - NTHREADS)   // tid < 128
        atomicAdd(&sh_dk[k2], dacc1);

    // ---- cross-group reduction of acc into sh_red ----
    float accf[K_T][C_T];
#pragma unroll
    for (int j = 0; j < K_T; j++)
#pragma unroll
        for (int q = 0; q < 4; q++)
            unpack2(acc[j][q], accf[j][2 * q], accf[j][2 * q + 1]);

    if (g == 1) {
#pragma unroll
        for (int j = 0; j < K_T; j++) {
            int k = kt * K_T + j;
#pragma unroll
            for (int q = 0; q < C_T; q++)
                sh_red[k * CC + ct * C_T + q] = accf[j][q];
        }
    }
    __syncthreads();
    if (g == 2) {
#pragma unroll
        for (int j = 0; j < K_T; j++) {
            int k = kt * K_T + j;
#pragma unroll
            for (int q = 0; q < C_T; q++)
                sh_red[k * CC + ct * C_T + q] += accf[j][q];
        }
    }
    __syncthreads();
    if (g == 3) {
#pragma unroll
        for (int j = 0; j < K_T; j++) {
            int k = kt * K_T + j;
#pragma unroll
            for (int q = 0; q < C_T; q++)
                sh_red[k * CC + ct * C_T + q] += accf[j][q];
        }
    }
    __syncthreads();
    if (g == 0) {
        float* outp = g_part + blockIdx.x * (KK * CC);
#pragma unroll
        for (int j = 0; j < K_T; j++) {
            int k = kt * K_T + j;
#pragma unroll
            for (int q = 0; q < C_T; q++)
                outp[k * CC + ct * C_T + q] =
                    accf[j][q] + sh_red[k * CC + ct * C_T + q];
        }
    }
    if (tid < KK)
        g_pden[blockIdx.x * KK + tid] = sh_dk[tid];
}

// ---------------------------------------------------------------------------
// out[b,k,c] = sum_s part / sum_s pden ; SPLITS compile-time -> full unroll
// ---------------------------------------------------------------------------
__global__ void reduce_kernel(float* __restrict__ out, int total) {
    const int i = blockIdx.x * blockDim.x + threadIdx.x;
    if (i >= total) return;
    const int c = i % CC;
    const int k = (i / CC) % KK;
    const int b = i / (KK * CC);

    float v = 0.0f, d = 0.0f;
#pragma unroll
    for (int s = 0; s < SPLITS; s++)
        v += g_part[((b * SPLITS + s) * KK + k) * CC + c];
#pragma unroll
    for (int s = 0; s < SPLITS; s++)
        d += g_pden[(b * SPLITS + s) * KK + k];
    out[i] = (d > 0.0f) ? v / d : 0.0f;
}

// ---------------------------------------------------------------------------
extern "C" void kernel_launch(void* const* d_in, const int* in_sizes, int n_in,
                              void* d_out, int out_size) {
    const float* feats = (const float*)d_in[0];   // [N, C]
    const float* probs = (const float*)d_in[1];   // [N, K]
    const int*   bidx  = (const int*)d_in[3];     // [N], sorted
    float* out = (float*)d_out;                   // [B, K, C]

    const int N = in_sizes[3];
    const int B = out_size / (KK * CC);

    gather_kernel<<<B * SPLITS, NTHREADS>>>(feats, probs, bidx, N);
    reduce_kernel<<<(out_size + 127) / 128, 128>>>(out, out_size);
}

// round 5
// speedup vs baseline: 1.6949x; 1.0693x over previous
#include <cuda_runtime.h>

#define KK 20
#define CC 96
#define TILE_P 16
#define NG 4
#define GROUP 48                 // 4 kt * 12 ct
#define NTHREADS (NG * GROUP)    // 192
#define K_T 5
#define C_T 8
#define SPLITS 37
#define MAX_BLOCKS 400
#define NSTAGE 4

__device__ float g_part[MAX_BLOCKS * KK * CC];
__device__ float g_pden[MAX_BLOCKS * KK];

// ---------------- f32x2 helpers ----------------
__device__ __forceinline__ unsigned long long pack2(float lo, float hi) {
    unsigned long long r;
    asm("mov.b64 %0, {%1, %2};" : "=l"(r) : "f"(lo), "f"(hi));
    return r;
}
__device__ __forceinline__ unsigned long long fma2(unsigned long long a,
                                                   unsigned long long b,
                                                   unsigned long long c) {
    unsigned long long d;
    asm("fma.rn.f32x2 %0, %1, %2, %3;" : "=l"(d) : "l"(a), "l"(b), "l"(c));
    return d;
}
__device__ __forceinline__ void unpack2(unsigned long long x, float& lo, float& hi) {
    asm("mov.b64 {%0, %1}, %2;" : "=f"(lo), "=f"(hi) : "l"(x));
}

// ---------------- TMA bulk + mbarrier helpers ----------------
__device__ __forceinline__ unsigned smem_u32(const void* p) {
    return (unsigned)__cvta_generic_to_shared(p);
}
__device__ __forceinline__ void mbar_init(unsigned mbar, unsigned count) {
    asm volatile("mbarrier.init.shared.b64 [%0], %1;" :: "r"(mbar), "r"(count) : "memory");
}
__device__ __forceinline__ void mbar_expect_tx(unsigned mbar, unsigned bytes) {
    asm volatile("mbarrier.arrive.expect_tx.shared.b64 _, [%0], %1;"
                 :: "r"(mbar), "r"(bytes) : "memory");
}
__device__ __forceinline__ void mbar_wait(unsigned mbar, unsigned parity) {
    asm volatile(
        "{\n\t.reg .pred P;\n"
        "WAIT_%=:\n\t"
        "mbarrier.try_wait.parity.acquire.cta.shared::cta.b64 P, [%0], %1, 0x989680;\n\t"
        "@!P bra WAIT_%=;\n\t"
        "}"
        :: "r"(mbar), "r"(parity) : "memory");
}
__device__ __forceinline__ void bulk_g2s(unsigned dst, const void* src,
                                         unsigned bytes, unsigned mbar) {
    asm volatile(
        "cp.async.bulk.shared::cta.global.mbarrier::complete_tx::bytes [%0], [%1], %2, [%3];"
        :: "r"(dst), "l"(src), "r"(bytes), "r"(mbar) : "memory");
}

// warp-cooperative lower_bound on sorted int array
__device__ __forceinline__ int lower_bound_warp(const int* __restrict__ a,
                                                int n, int key) {
    int lane = threadIdx.x & 31;
    int lo = 0, hi = n;
    while (lo < hi) {
        int len = hi - lo;
        int chunk = (len + 31) >> 5;
        int pos = lo + lane * chunk;
        bool pred = (pos < hi) && (a[pos] < key);
        unsigned m = __ballot_sync(0xffffffffu, pred);
        int t = __popc(m);
        if (t == 0) { hi = lo; break; }
        int nlo = lo + (t - 1) * chunk + 1;
        int nhi = (t < 32) ? min(lo + t * chunk, hi) : hi;
        lo = nlo; hi = nhi;
    }
    return lo;
}

// ---------------------------------------------------------------------------
__global__ void __launch_bounds__(NTHREADS)
gather_kernel(const float* __restrict__ feats,
              const float* __restrict__ probs,
              const int*   __restrict__ bidx,
              int N) {
    __shared__ float raw_f[NSTAGE][TILE_P][CC];     // 24576 B
    __shared__ float raw_p[NSTAGE][TILE_P][KK];     //  5120 B
    __shared__ float sh_ep[TILE_P][32];             //  2048 B  (kt-padded exp)
    __shared__ float sh_red[KK * CC];               //  7680 B
    __shared__ float sh_dk[KK];
    __shared__ int   sh_off[2];
    __shared__ alignas(8) unsigned long long mbar[NSTAGE];

    const int tid = threadIdx.x;
    const int b = blockIdx.x / SPLITS;
    const int s = blockIdx.x % SPLITS;

    if (tid < 32) {
        int lo0 = lower_bound_warp(bidx, N, b);
        int lo1 = lower_bound_warp(bidx, N, b + 1);
        if (tid == 0) { sh_off[0] = lo0; sh_off[1] = lo1; }
    }
    if (tid < KK) sh_dk[tid] = 0.0f;
    if (tid == 0) {
#pragma unroll
        for (int i = 0; i < NSTAGE; i++) mbar_init(smem_u32(&mbar[i]), 1);
    }
    __syncthreads();

    const int seg0 = sh_off[0];
    const int seg1 = sh_off[1];
    const int len  = seg1 - seg0;
    const int r0 = seg0 + (int)((long long)len * s / SPLITS);
    const int r1 = seg0 + (int)((long long)len * (s + 1) / SPLITS);
    const int T  = (r1 - r0 + TILE_P - 1) / TILE_P;

    const int g  = tid / GROUP;
    const int gt = tid % GROUP;
    const int kt = gt / 12;
    const int ct = gt % 12;

    unsigned long long acc[K_T][4];
#pragma unroll
    for (int j = 0; j < K_T; j++)
#pragma unroll
        for (int q = 0; q < 4; q++) acc[j][q] = 0ULL;
    float dacc0 = 0.0f, dacc1 = 0.0f;
    const int k1 = tid % KK;
    const int k2 = (tid + NTHREADS) % KK;

    // ---- prologue: issue up to 3 tiles ----
    if (tid == 0) {
        int np = min(NSTAGE - 1, T);
        for (int tt = 0; tt < np; tt++) {
            int base = r0 + tt * TILE_P;
            int rows = min(TILE_P, N - base);
            unsigned fb = rows * CC * 4;
            unsigned pb = rows * KK * 4;
            unsigned mb = smem_u32(&mbar[tt]);
            mbar_expect_tx(mb, fb + pb);
            bulk_g2s(smem_u32(&raw_f[tt][0][0]), feats + (long long)base * CC, fb, mb);
            bulk_g2s(smem_u32(&raw_p[tt][0][0]), probs + (long long)base * KK, pb, mb);
        }
    }

    for (int t = 0; t < T; t++) {
        const int st = t & (NSTAGE - 1);
        const int base = r0 + t * TILE_P;
        mbar_wait(smem_u32(&mbar[st]), (t >> 2) & 1);

        // convert probs -> exp (masked, kt-padded), accumulate denom
        {
            int v = tid;
            if (v < TILE_P * KK) {
                int p = v / KK, k = v % KK;
                float e = (base + p < r1) ? __expf(raw_p[st][p][k]) : 0.0f;
                sh_ep[p][(k / K_T) * 8 + (k % K_T)] = e;
                dacc0 += e;
            }
            v = tid + NTHREADS;
            if (v < TILE_P * KK) {
                int p = v / KK, k = v % KK;
                float e = (base + p < r1) ? __expf(raw_p[st][p][k]) : 0.0f;
                sh_ep[p][(k / K_T) * 8 + (k % K_T)] = e;
                dacc1 += e;
            }
        }
        __syncthreads();

        // ---- rank-16 update (FFMA2) ----
#pragma unroll
        for (int p = 0; p < TILE_P / NG; p++) {
            const int pp = g * (TILE_P / NG) + p;
            const ulonglong2* rowf =
                reinterpret_cast<const ulonglong2*>(&raw_f[st][pp][ct * C_T]);
            ulonglong2 fA = rowf[0];
            ulonglong2 fB = rowf[1];
            float4 e03 = *reinterpret_cast<const float4*>(&sh_ep[pp][kt * 8]);
            float  e4  = sh_ep[pp][kt * 8 + 4];
            unsigned long long e2[K_T];
            e2[0] = pack2(e03.x, e03.x);
            e2[1] = pack2(e03.y, e03.y);
            e2[2] = pack2(e03.z, e03.z);
            e2[3] = pack2(e03.w, e03.w);
            e2[4] = pack2(e4, e4);
#pragma unroll
            for (int j = 0; j < K_T; j++) {
                acc[j][0] = fma2(e2[j], fA.x, acc[j][0]);
                acc[j][1] = fma2(e2[j], fA.y, acc[j][1]);
                acc[j][2] = fma2(e2[j], fB.x, acc[j][2]);
                acc[j][3] = fma2(e2[j], fB.y, acc[j][3]);
            }
        }
        __syncthreads();   // stage st fully consumed

        // issue tile t+3 into the stage freed at t-1
        if (tid == 0 && t + NSTAGE - 1 < T) {
            int tt = t + NSTAGE - 1;
            int nst = tt & (NSTAGE - 1);
            int nb = r0 + tt * TILE_P;
            int rows = min(TILE_P, N - nb);
            unsigned fb = rows * CC * 4;
            unsigned pb = rows * KK * 4;
            unsigned mb = smem_u32(&mbar[nst]);
            mbar_expect_tx(mb, fb + pb);
            bulk_g2s(smem_u32(&raw_f[nst][0][0]), feats + (long long)nb * CC, fb, mb);
            bulk_g2s(smem_u32(&raw_p[nst][0][0]), probs + (long long)nb * KK, pb, mb);
        }
    }

    // ---- denom reduction ----
    atomicAdd(&sh_dk[k1], dacc0);
    if (tid < TILE_P * KK - NTHREADS)          // tid < 128
        atomicAdd(&sh_dk[k2], dacc1);

    // ---- cross-group reduction of acc into sh_red ----
    float accf[K_T][C_T];
#pragma unroll
    for (int j = 0; j < K_T; j++)
#pragma unroll
        for (int q = 0; q < 4; q++)
            unpack2(acc[j][q], accf[j][2 * q], accf[j][2 * q + 1]);

    if (g == 1) {
#pragma unroll
        for (int j = 0; j < K_T; j++) {
            int k = kt * K_T + j;
#pragma unroll
            for (int q = 0; q < C_T; q++)
                sh_red[k * CC + ct * C_T + q] = accf[j][q];
        }
    }
    __syncthreads();
    if (g == 2) {
#pragma unroll
        for (int j = 0; j < K_T; j++) {
            int k = kt * K_T + j;
#pragma unroll
            for (int q = 0; q < C_T; q++)
                sh_red[k * CC + ct * C_T + q] += accf[j][q];
        }
    }
    __syncthreads();
    if (g == 3) {
#pragma unroll
        for (int j = 0; j < K_T; j++) {
            int k = kt * K_T + j;
#pragma unroll
            for (int q = 0; q < C_T; q++)
                sh_red[k * CC + ct * C_T + q] += accf[j][q];
        }
    }
    __syncthreads();
    if (g == 0) {
        float* outp = g_part + blockIdx.x * (KK * CC);
#pragma unroll
        for (int j = 0; j < K_T; j++) {
            int k = kt * K_T + j;
#pragma unroll
            for (int q = 0; q < C_T; q++)
                outp[k * CC + ct * C_T + q] =
                    accf[j][q] + sh_red[k * CC + ct * C_T + q];
        }
    }
    if (tid < KK)
        g_pden[blockIdx.x * KK + tid] = sh_dk[tid];
}

// ---------------------------------------------------------------------------
// reduce v2: one thread per float4 of output; fully unrolled 37-way sums.
// ---------------------------------------------------------------------------
__global__ void __launch_bounds__(128, 1)
reduce_kernel(float* __restrict__ out, int total4) {
    const int i = blockIdx.x * blockDim.x + threadIdx.x;
    if (i >= total4) return;
    const int c4 = i % (CC / 4);
    const int k  = (i / (CC / 4)) % KK;
    const int b  = i / (KK * CC / 4);

    const float4* p4 = reinterpret_cast<const float4*>(g_part);
    float4 v0 = make_float4(0.f, 0.f, 0.f, 0.f);
    float4 v1 = make_float4(0.f, 0.f, 0.f, 0.f);
    float d0 = 0.0f, d1 = 0.0f;
#pragma unroll
    for (int s = 0; s < SPLITS - 1; s += 2) {
        float4 a = p4[((b * SPLITS + s)     * KK + k) * (CC / 4) + c4];
        float4 c = p4[((b * SPLITS + s + 1) * KK + k) * (CC / 4) + c4];
        v0.x += a.x; v0.y += a.y; v0.z += a.z; v0.w += a.w;
        v1.x += c.x; v1.y += c.y; v1.z += c.z; v1.w += c.w;
        d0 += g_pden[(b * SPLITS + s) * KK + k];
        d1 += g_pden[(b * SPLITS + s + 1) * KK + k];
    }
    {
        int s = SPLITS - 1;
        float4 a = p4[((b * SPLITS + s) * KK + k) * (CC / 4) + c4];
        v0.x += a.x; v0.y += a.y; v0.z += a.z; v0.w += a.w;
        d0 += g_pden[(b * SPLITS + s) * KK + k];
    }
    float d = d0 + d1;
    float inv = (d > 0.0f) ? 1.0f / d : 0.0f;
    float4 r;
    r.x = (v0.x + v1.x) * inv;
    r.y = (v0.y + v1.y) * inv;
    r.z = (v0.z + v1.z) * inv;
    r.w = (v0.w + v1.w) * inv;
    reinterpret_cast<float4*>(out)[i] = r;
}

// ---------------------------------------------------------------------------
extern "C" void kernel_launch(void* const* d_in, const int* in_sizes, int n_in,
                              void* d_out, int out_size) {
    const float* feats = (const float*)d_in[0];   // [N, C]
    const float* probs = (const float*)d_in[1];   // [N, K]
    const int*   bidx  = (const int*)d_in[3];     // [N], sorted
    float* out = (float*)d_out;                   // [B, K, C]

    const int N = in_sizes[3];
    const int B = out_size / (KK * CC);

    gather_kernel<<<B * SPLITS, NTHREADS>>>(feats, probs, bidx, N);
    int total4 = out_size / 4;
    reduce_kernel<<<(total4 + 127) / 128, 128>>>(out, total4);
}

// round 6
// speedup vs baseline: 1.8062x; 1.0656x over previous
#include <cuda_runtime.h>

#define KK 20
#define CC 96
#define TILE_P 32
#define NG 4
#define GROUP 48                 // 4 kt * 12 ct
#define NTHREADS (NG * GROUP)    // 192
#define K_T 5
#define C_T 8
#define SPLITS 37
#define MAX_BLOCKS 400
#define NSTAGE 5

// dynamic smem layout (floats)
#define OFF_MBAR   0                                   // 16 floats (5 u64 + pad)
#define OFF_RAWF   16                                  // NSTAGE*TILE_P*CC
#define OFF_RAWP   (OFF_RAWF + NSTAGE * TILE_P * CC)   // NSTAGE*TILE_P*KK
#define OFF_EP     (OFF_RAWP + NSTAGE * TILE_P * KK)   // TILE_P*32
#define OFF_RED    (OFF_EP + TILE_P * 32)              // KK*CC
#define OFF_DK     (OFF_RED + KK * CC)                 // 32
#define SMEM_FLOATS (OFF_DK + 32)
#define SMEM_BYTES (SMEM_FLOATS * 4)

__device__ float g_part[MAX_BLOCKS * KK * CC];
__device__ float g_pden[MAX_BLOCKS * KK];

// ---------------- f32x2 helpers ----------------
__device__ __forceinline__ unsigned long long pack2(float lo, float hi) {
    unsigned long long r;
    asm("mov.b64 %0, {%1, %2};" : "=l"(r) : "f"(lo), "f"(hi));
    return r;
}
__device__ __forceinline__ unsigned long long fma2(unsigned long long a,
                                                   unsigned long long b,
                                                   unsigned long long c) {
    unsigned long long d;
    asm("fma.rn.f32x2 %0, %1, %2, %3;" : "=l"(d) : "l"(a), "l"(b), "l"(c));
    return d;
}
__device__ __forceinline__ void unpack2(unsigned long long x, float& lo, float& hi) {
    asm("mov.b64 {%0, %1}, %2;" : "=f"(lo), "=f"(hi) : "l"(x));
}

// ---------------- TMA bulk + mbarrier helpers ----------------
__device__ __forceinline__ unsigned smem_u32(const void* p) {
    return (unsigned)__cvta_generic_to_shared(p);
}
__device__ __forceinline__ void mbar_init(unsigned mbar, unsigned count) {
    asm volatile("mbarrier.init.shared.b64 [%0], %1;" :: "r"(mbar), "r"(count) : "memory");
}
__device__ __forceinline__ void mbar_expect_tx(unsigned mbar, unsigned bytes) {
    asm volatile("mbarrier.arrive.expect_tx.shared.b64 _, [%0], %1;"
                 :: "r"(mbar), "r"(bytes) : "memory");
}
__device__ __forceinline__ void mbar_wait(unsigned mbar, unsigned parity) {
    asm volatile(
        "{\n\t.reg .pred P;\n"
        "WAIT_%=:\n\t"
        "mbarrier.try_wait.parity.acquire.cta.shared::cta.b64 P, [%0], %1, 0x989680;\n\t"
        "@!P bra WAIT_%=;\n\t"
        "}"
        :: "r"(mbar), "r"(parity) : "memory");
}
__device__ __forceinline__ void bulk_g2s(unsigned dst, const void* src,
                                         unsigned bytes, unsigned mbar) {
    asm volatile(
        "cp.async.bulk.shared::cta.global.mbarrier::complete_tx::bytes [%0], [%1], %2, [%3];"
        :: "r"(dst), "l"(src), "r"(bytes), "r"(mbar) : "memory");
}

// warp-cooperative lower_bound on sorted int array
__device__ __forceinline__ int lower_bound_warp(const int* __restrict__ a,
                                                int n, int key) {
    int lane = threadIdx.x & 31;
    int lo = 0, hi = n;
    while (lo < hi) {
        int len = hi - lo;
        int chunk = (len + 31) >> 5;
        int pos = lo + lane * chunk;
        bool pred = (pos < hi) && (a[pos] < key);
        unsigned m = __ballot_sync(0xffffffffu, pred);
        int t = __popc(m);
        if (t == 0) { hi = lo; break; }
        int nlo = lo + (t - 1) * chunk + 1;
        int nhi = (t < 32) ? min(lo + t * chunk, hi) : hi;
        lo = nlo; hi = nhi;
    }
    return lo;
}

// ---------------------------------------------------------------------------
__global__ void __launch_bounds__(NTHREADS)
gather_kernel(const float* __restrict__ feats,
              const float* __restrict__ probs,
              const int*   __restrict__ bidx,
              int N) {
    extern __shared__ float smem[];
    unsigned long long* mbar = reinterpret_cast<unsigned long long*>(smem + OFF_MBAR);
    float* raw_f = smem + OFF_RAWF;     // [NSTAGE][TILE_P][CC]
    float* raw_p = smem + OFF_RAWP;     // [NSTAGE][TILE_P][KK]
    float* sh_ep = smem + OFF_EP;       // [TILE_P][32] kt-padded exp
    float* sh_red = smem + OFF_RED;     // [KK*CC]
    float* sh_dk = smem + OFF_DK;       // [KK]
    __shared__ int sh_off[2];

    const int tid = threadIdx.x;
    const int b = blockIdx.x / SPLITS;
    const int s = blockIdx.x % SPLITS;

    if (tid < 32) {
        int lo0 = lower_bound_warp(bidx, N, b);
        int lo1 = lower_bound_warp(bidx, N, b + 1);
        if (tid == 0) { sh_off[0] = lo0; sh_off[1] = lo1; }
    }
    if (tid < KK) sh_dk[tid] = 0.0f;
    if (tid == 0) {
#pragma unroll
        for (int i = 0; i < NSTAGE; i++) mbar_init(smem_u32(&mbar[i]), 1);
    }
    __syncthreads();

    const int seg0 = sh_off[0];
    const int seg1 = sh_off[1];
    const int len  = seg1 - seg0;
    const int r0 = seg0 + (int)((long long)len * s / SPLITS);
    const int r1 = seg0 + (int)((long long)len * (s + 1) / SPLITS);
    const int T  = (r1 - r0 + TILE_P - 1) / TILE_P;

    const int g  = tid / GROUP;
    const int gt = tid % GROUP;
    const int kt = gt / 12;
    const int ct = gt % 12;

    unsigned long long acc[K_T][4];
#pragma unroll
    for (int j = 0; j < K_T; j++)
#pragma unroll
        for (int q = 0; q < 4; q++) acc[j][q] = 0ULL;
    float dacc[4] = {0.f, 0.f, 0.f, 0.f};

    // ---- prologue: issue up to NSTAGE-1 tiles ----
    if (tid == 0) {
        int np = min(NSTAGE - 1, T);
        for (int tt = 0; tt < np; tt++) {
            int base = r0 + tt * TILE_P;
            int rows = min(TILE_P, N - base);
            unsigned fb = rows * CC * 4;
            unsigned pb = rows * KK * 4;
            unsigned mb = smem_u32(&mbar[tt]);
            mbar_expect_tx(mb, fb + pb);
            bulk_g2s(smem_u32(&raw_f[tt * TILE_P * CC]),
                     feats + (long long)base * CC, fb, mb);
            bulk_g2s(smem_u32(&raw_p[tt * TILE_P * KK]),
                     probs + (long long)base * KK, pb, mb);
        }
    }

    int st = 0, par = 0;
    for (int t = 0; t < T; t++) {
        const int base = r0 + t * TILE_P;
        mbar_wait(smem_u32(&mbar[st]), par);

        // convert probs -> exp (masked, kt-padded), accumulate denom
#pragma unroll
        for (int j = 0; j < 4; j++) {
            int v = tid + j * NTHREADS;
            if (v < TILE_P * KK) {
                int p = v / KK, k = v % KK;
                float e = (base + p < r1)
                        ? __expf(raw_p[st * TILE_P * KK + p * KK + k]) : 0.0f;
                sh_ep[p * 32 + (k / K_T) * 8 + (k % K_T)] = e;
                dacc[j] += e;
            }
        }
        __syncthreads();

        // ---- rank-32 update (FFMA2) ----
#pragma unroll
        for (int p = 0; p < TILE_P / NG; p++) {
            const int pp = g * (TILE_P / NG) + p;
            const ulonglong2* rowf = reinterpret_cast<const ulonglong2*>(
                &raw_f[st * TILE_P * CC + pp * CC + ct * C_T]);
            ulonglong2 fA = rowf[0];
            ulonglong2 fB = rowf[1];
            float4 e03 = *reinterpret_cast<const float4*>(&sh_ep[pp * 32 + kt * 8]);
            float  e4  = sh_ep[pp * 32 + kt * 8 + 4];
            unsigned long long e2[K_T];
            e2[0] = pack2(e03.x, e03.x);
            e2[1] = pack2(e03.y, e03.y);
            e2[2] = pack2(e03.z, e03.z);
            e2[3] = pack2(e03.w, e03.w);
            e2[4] = pack2(e4, e4);
#pragma unroll
            for (int j = 0; j < K_T; j++) {
                acc[j][0] = fma2(e2[j], fA.x, acc[j][0]);
                acc[j][1] = fma2(e2[j], fA.y, acc[j][1]);
                acc[j][2] = fma2(e2[j], fB.x, acc[j][2]);
                acc[j][3] = fma2(e2[j], fB.y, acc[j][3]);
            }
        }
        __syncthreads();   // stage st fully consumed

        // issue tile t+NSTAGE-1 into the stage freed at t-1
        if (tid == 0 && t + NSTAGE - 1 < T) {
            int tt = t + NSTAGE - 1;
            int nst = st == 0 ? NSTAGE - 1 : st - 1;
            int nb = r0 + tt * TILE_P;
            int rows = min(TILE_P, N - nb);
            unsigned fb = rows * CC * 4;
            unsigned pb = rows * KK * 4;
            unsigned mb = smem_u32(&mbar[nst]);
            mbar_expect_tx(mb, fb + pb);
            bulk_g2s(smem_u32(&raw_f[nst * TILE_P * CC]),
                     feats + (long long)nb * CC, fb, mb);
            bulk_g2s(smem_u32(&raw_p[nst * TILE_P * KK]),
                     probs + (long long)nb * KK, pb, mb);
        }
        if (++st == NSTAGE) { st = 0; par ^= 1; }
    }

    // ---- denom reduction (k index fixed per j-slot) ----
#pragma unroll
    for (int j = 0; j < 4; j++) {
        int v = tid + j * NTHREADS;
        if (v < TILE_P * KK)
            atomicAdd(&sh_dk[v % KK], dacc[j]);
    }

    // ---- cross-group reduction of acc into sh_red ----
    float accf[K_T][C_T];
#pragma unroll
    for (int j = 0; j < K_T; j++)
#pragma unroll
        for (int q = 0; q < 4; q++)
            unpack2(acc[j][q], accf[j][2 * q], accf[j][2 * q + 1]);

    if (g == 1) {
#pragma unroll
        for (int j = 0; j < K_T; j++) {
            int k = kt * K_T + j;
#pragma unroll
            for (int q = 0; q < C_T; q++)
                sh_red[k * CC + ct * C_T + q] = accf[j][q];
        }
    }
    __syncthreads();
    if (g == 2) {
#pragma unroll
        for (int j = 0; j < K_T; j++) {
            int k = kt * K_T + j;
#pragma unroll
            for (int q = 0; q < C_T; q++)
                sh_red[k * CC + ct * C_T + q] += accf[j][q];
        }
    }
    __syncthreads();
    if (g == 3) {
#pragma unroll
        for (int j = 0; j < K_T; j++) {
            int k = kt * K_T + j;
#pragma unroll
            for (int q = 0; q < C_T; q++)
                sh_red[k * CC + ct * C_T + q] += accf[j][q];
        }
    }
    __syncthreads();
    if (g == 0) {
        float* outp = g_part + blockIdx.x * (KK * CC);
#pragma unroll
        for (int j = 0; j < K_T; j++) {
            int k = kt * K_T + j;
#pragma unroll
            for (int q = 0; q < C_T; q++)
                outp[k * CC + ct * C_T + q] =
                    accf[j][q] + sh_red[k * CC + ct * C_T + q];
        }
    }
    if (tid < KK)
        g_pden[blockIdx.x * KK + tid] = sh_dk[tid];
}

// ---------------------------------------------------------------------------
// reduce v3: one block per (b,k); 4 s-slices x 96 channels; smem combine.
// ---------------------------------------------------------------------------
__global__ void __launch_bounds__(384, 4)
reduce_kernel(float* __restrict__ out) {
    const int bk = blockIdx.x;          // B*KK blocks
    const int b = bk / KK, k = bk % KK;
    const int sg = threadIdx.x / CC;    // 0..3
    const int c  = threadIdx.x % CC;

    __shared__ float red[4][CC];
    __shared__ float den[4];

    float v = 0.0f, d = 0.0f;
#pragma unroll
    for (int s = sg; s < SPLITS; s += 4) {
        v += g_part[((b * SPLITS + s) * KK + k) * CC + c];
        if (c == 0) d += g_pden[(b * SPLITS + s) * KK + k];
    }
    red[sg][c] = v;
    if (c == 0) den[sg] = d;
    __syncthreads();

    if (threadIdx.x < CC) {
        float vv = red[0][c] + red[1][c] + red[2][c] + red[3][c];
        float dd = den[0] + den[1] + den[2] + den[3];
        out[bk * CC + c] = (dd > 0.0f) ? vv / dd : 0.0f;
    }
}

// ---------------------------------------------------------------------------
extern "C" void kernel_launch(void* const* d_in, const int* in_sizes, int n_in,
                              void* d_out, int out_size) {
    const float* feats = (const float*)d_in[0];   // [N, C]
    const float* probs = (const float*)d_in[1];   // [N, K]
    const int*   bidx  = (const int*)d_in[3];     // [N], sorted
    float* out = (float*)d_out;                   // [B, K, C]

    const int N = in_sizes[3];
    const int B = out_size / (KK * CC);

    cudaFuncSetAttribute(gather_kernel,
                         cudaFuncAttributeMaxDynamicSharedMemorySize, SMEM_BYTES);
    gather_kernel<<<B * SPLITS, NTHREADS, SMEM_BYTES>>>(feats, probs, bidx, N);
    reduce_kernel<<<B * KK, 384>>>(out);
}